// round 17
// baseline (speedup 1.0000x reference)
#include <cuda_runtime.h>

#define D_ 4
#define R_ 32
#define F_ 8
#define U_ 64
#define B_ 512

typedef unsigned long long ull;

// ---------- packed f32x2 helpers (SASS FFMA2) ----------
static __device__ __forceinline__ ull pk2(float lo, float hi) {
    ull r; asm("mov.b64 %0, {%1, %2};" : "=l"(r) : "f"(lo), "f"(hi)); return r;
}
static __device__ __forceinline__ void upk2(ull v, float& lo, float& hi) {
    asm("mov.b64 {%0, %1}, %2;" : "=f"(lo), "=f"(hi) : "l"(v));
}
static __device__ __forceinline__ ull fma2_(ull a, ull b, ull c) {
    ull d; asm("fma.rn.f32x2 %0, %1, %2, %3;" : "=l"(d) : "l"(a), "l"(b), "l"(c)); return d;
}
static __device__ __forceinline__ ull mul2_(ull a, ull b) {
    ull d; asm("mul.rn.f32x2 %0, %1, %2;" : "=l"(d) : "l"(a), "l"(b)); return d;
}
static __device__ __forceinline__ ull add2_(ull a, ull b) {
    ull d; asm("add.rn.f32x2 %0, %1, %2;" : "=l"(d) : "l"(a), "l"(b)); return d;
}

// Pair-merged products. Only the orientation each stage needs is materialized:
//   p in {0,1}: g_KK [u][p][c][j*32+k]   (row-major)
//   p in {2,3}: g_KKT[u][p][c][k*32+j]   (transposed)
__device__ float g_KK [U_ * 4 * 16 * 1024];   // 16 MB
__device__ float g_KKT[U_ * 4 * 16 * 1024];   // 16 MB

#define PITCH 36

// Register-tiled 32x32x32 matmul: C = A @ B, operands pitch-36 in smem.
// Lane (r = lane>>2, c = lane&3): rows {r,r+8,r+16,r+24} x cols {8c..8c+7}.
static __device__ __forceinline__ void mmk(const float* A, const float* B,
                                           int r, int c, ull acc[16]) {
    #pragma unroll
    for (int i = 0; i < 16; i++) acc[i] = 0ull;
    #pragma unroll
    for (int k4 = 0; k4 < 8; k4++) {
        float4 av[4];
        #pragma unroll
        for (int rho = 0; rho < 4; rho++)
            av[rho] = *(const float4*)(A + (r + 8 * rho) * PITCH + 4 * k4);
        ulonglong2 bv[4][2];
        #pragma unroll
        for (int kp = 0; kp < 4; kp++) {
            bv[kp][0] = *(const ulonglong2*)(B + (4 * k4 + kp) * PITCH + 8 * c);
            bv[kp][1] = *(const ulonglong2*)(B + (4 * k4 + kp) * PITCH + 8 * c + 4);
        }
        #pragma unroll
        for (int rho = 0; rho < 4; rho++) {
            const float* af = (const float*)&av[rho];
            #pragma unroll
            for (int kp = 0; kp < 4; kp++) {
                const ull a2 = pk2(af[kp], af[kp]);
                acc[rho * 4 + 0] = fma2_(a2, bv[kp][0].x, acc[rho * 4 + 0]);
                acc[rho * 4 + 1] = fma2_(a2, bv[kp][0].y, acc[rho * 4 + 1]);
                acc[rho * 4 + 2] = fma2_(a2, bv[kp][1].x, acc[rho * 4 + 2]);
                acc[rho * 4 + 3] = fma2_(a2, bv[kp][1].y, acc[rho * 4 + 3]);
            }
        }
    }
}

// ---------------------------------------------------------------------------
// Precompute (UNCHANGED from the proven R16 version, ~11 us).
// 128 blocks = (u-pair, p), 512 threads; float2 staging across adjacent u;
// register-tiled mmk per warp; orientation-selective writes.
// ---------------------------------------------------------------------------
#define PAS 9216           // 2 * 4 * 1152
#define PRE_FLOATS (2 * PAS + 16 * 1056)

__global__ __launch_bounds__(512) void kk_precompute(const float* __restrict__ K) {
    extern __shared__ float ps[];
    float* As = ps;                 // [uu][d][row*36+col]
    float* Bs = ps + PAS;           // [uu][d][row*36+col]
    float* Ts = ps + 2 * PAS;       // [warp][1056] transpose staging (pitch 33)
    const int pr = blockIdx.x >> 2;        // u-pair 0..31
    const int p  = blockIdx.x & 3;
    const int u0 = pr * 2;
    const int tid = threadIdx.x;

    #pragma unroll
    for (int d = 0; d < 4; d++)
        #pragma unroll
        for (int e0 = 0; e0 < 1024; e0 += 512) {
            const int e = e0 + tid;
            const float2 va = *(const float2*)&K[((size_t)(d * 1024 + e) * 8 + 2 * p) * 64 + u0];
            const float2 vb = *(const float2*)&K[((size_t)(d * 1024 + e) * 8 + 2 * p + 1) * 64 + u0];
            const int idx = d * 1152 + (e >> 5) * PITCH + (e & 31);
            As[idx]        = va.x;
            As[4608 + idx] = va.y;
            Bs[idx]        = vb.x;
            Bs[4608 + idx] = vb.y;
        }
    __syncthreads();

    const int w = tid >> 5, lane = tid & 31;
    const int r = lane >> 2, cc = lane & 3;
    const int d0 = w >> 2, d1 = w & 3;

    #pragma unroll 1
    for (int uu = 0; uu < 2; uu++) {
        ull acc[16];
        mmk(As + uu * 4608 + d0 * 1152, Bs + uu * 4608 + d1 * 1152, r, cc, acc);

        const int u = u0 + uu;
        if (p < 2) {
            float* dst = g_KK + (((u * 4 + p) * 16 + w) * 1024);
            #pragma unroll
            for (int rho = 0; rho < 4; rho++) {
                float4 o0, o1;
                upk2(acc[rho * 4 + 0], o0.x, o0.y); upk2(acc[rho * 4 + 1], o0.z, o0.w);
                upk2(acc[rho * 4 + 2], o1.x, o1.y); upk2(acc[rho * 4 + 3], o1.z, o1.w);
                *(float4*)(dst + (r + 8 * rho) * 32 + 8 * cc)     = o0;
                *(float4*)(dst + (r + 8 * rho) * 32 + 8 * cc + 4) = o1;
            }
        } else {
            float* Tw = Ts + w * 1056;
            #pragma unroll
            for (int rho = 0; rho < 4; rho++) {
                const int row = r + 8 * rho;
                #pragma unroll
                for (int gp = 0; gp < 4; gp++) {
                    float lo, hi;
                    upk2(acc[rho * 4 + gp], lo, hi);
                    Tw[(8 * cc + 2 * gp) * 33 + row]     = lo;
                    Tw[(8 * cc + 2 * gp + 1) * 33 + row] = hi;
                }
            }
            __syncwarp();
            float* kt = g_KKT + (((u * 4 + p) * 16 + w) * 1024);
            #pragma unroll
            for (int i = 0; i < 32; i++)
                kt[i * 32 + lane] = Tw[i * 33 + lane];
            __syncwarp();
        }
    }
}

// ---------------------------------------------------------------------------
// Main. Block = 256 threads = 8 warps, one u, 8 b (warp w owns b = b0+w).
// Smem (floats): W[512] | SL[8*1152] | SR[8*1152]   (~74 KB, 2 CTAs/SM)
// Rolling half-set (16-reg) KK prefetch: kk0 hidden behind W/sync, kk2-h0
// hidden behind mm1, kk1/kk3 chained behind prior build compute. Arithmetic
// order identical to R16 (h-split, add2-merged).
// ---------------------------------------------------------------------------
#define SLOT  1152
#define OFF_SL  512
#define OFF_SR  (OFF_SL + 8 * SLOT)
#define SMEM_FLOATS (OFF_SR + 8 * SLOT)

static __device__ __forceinline__ void load_half(const float* g, int e, int h,
                                                 ulonglong2 kk[8]) {
    const ulonglong2* base = (const ulonglong2*)g;
    #pragma unroll
    for (int cc = 0; cc < 8; cc++) kk[cc] = base[(h * 8 + cc) * 256 + e];
}

// Process one 8-c half for all 8 b. FIRST=1 initializes acc, else accumulates.
template <int FIRST>
static __device__ __forceinline__ void build_half(const ulonglong2 kk[8], int p,
                                                  int hoff, const float* Wsm,
                                                  ull acc[8][2]) {
    #pragma unroll
    for (int b = 0; b < 8; b++) {
        const float4* wp = (const float4*)(Wsm + (b * 4 + p) * 16 + hoff);
        const float4 wa = wp[0], wb = wp[1];     // broadcast
        const ull q0 = pk2(wa.x, wa.x), q1 = pk2(wa.y, wa.y);
        const ull q2 = pk2(wa.z, wa.z), q3 = pk2(wa.w, wa.w);
        const ull q4 = pk2(wb.x, wb.x), q5 = pk2(wb.y, wb.y);
        const ull q6 = pk2(wb.z, wb.z), q7 = pk2(wb.w, wb.w);
        ull ax0 = mul2_(q0, kk[0].x), ay0 = mul2_(q0, kk[0].y);
        ull ax1 = mul2_(q1, kk[1].x), ay1 = mul2_(q1, kk[1].y);
        ax0 = fma2_(q2, kk[2].x, ax0);  ay0 = fma2_(q2, kk[2].y, ay0);
        ax1 = fma2_(q3, kk[3].x, ax1);  ay1 = fma2_(q3, kk[3].y, ay1);
        ax0 = fma2_(q4, kk[4].x, ax0);  ay0 = fma2_(q4, kk[4].y, ay0);
        ax1 = fma2_(q5, kk[5].x, ax1);  ay1 = fma2_(q5, kk[5].y, ay1);
        ax0 = fma2_(q6, kk[6].x, ax0);  ay0 = fma2_(q6, kk[6].y, ay0);
        ax1 = fma2_(q7, kk[7].x, ax1);  ay1 = fma2_(q7, kk[7].y, ay1);
        const ull sx = add2_(ax0, ax1), sy = add2_(ay0, ay1);
        if (FIRST) { acc[b][0] = sx; acc[b][1] = sy; }
        else { acc[b][0] = add2_(acc[b][0], sx); acc[b][1] = add2_(acc[b][1], sy); }
    }
}

static __device__ __forceinline__ void store_S(const ull acc[8][2], int e, float* dst) {
    const int j = e >> 3, k4 = e & 7;
    #pragma unroll
    for (int b = 0; b < 8; b++) {
        float4 o;
        upk2(acc[b][0], o.x, o.y); upk2(acc[b][1], o.z, o.w);
        *(float4*)(dst + b * SLOT + j * PITCH + 4 * k4) = o;
    }
}

__global__ __launch_bounds__(256, 2) void ring_main(const float* __restrict__ X,
                                                    float* __restrict__ out) {
    extern __shared__ float smem[];
    float* Wsm = smem;
    float* SL  = smem + OFF_SL;
    float* SR  = smem + OFF_SR;

    const int tid = threadIdx.x, w = tid >> 5, lane = tid & 31;
    const int r = lane >> 2, c = lane & 3;
    const int u = blockIdx.x >> 6;
    const int b0 = (blockIdx.x & 63) * 8;

    const float* KK0 = g_KK  + (size_t)((u * 4 + 0) * 16) * 1024;
    const float* KK1 = g_KK  + (size_t)((u * 4 + 1) * 16) * 1024;
    const float* KT2 = g_KKT + (size_t)((u * 4 + 2) * 16) * 1024;
    const float* KT3 = g_KKT + (size_t)((u * 4 + 3) * 16) * 1024;

    // ---- prefetch full kk0 (nothing else live); hidden behind W + sync
    ulonglong2 ka[8], kb[8];
    load_half(KK0, tid, 0, ka);
    load_half(KK0, tid, 1, kb);

    // W[b][p][c=(d0,d1)] = x[2p,d0] * x[2p+1,d1], straight from global X
    #pragma unroll
    for (int i = tid; i < 512; i += 256) {
        const int bb = i >> 6, pp = (i >> 4) & 3, cc = i & 15;
        Wsm[i] = X[(b0 + bb) * 32 + 8 * pp + (cc >> 2)] *
                 X[(b0 + bb) * 32 + 8 * pp + 4 + (cc & 3)];
    }
    __syncthreads();

    // ---- phase 1 builds: S0 -> SL, S1 -> SR; kk1 loads chained behind compute
    ull acc[8][2];
    build_half<1>(ka, 0, 0, Wsm, acc);
    load_half(KK1, tid, 0, ka);
    build_half<0>(kb, 0, 8, Wsm, acc);
    load_half(KK1, tid, 1, kb);
    store_S(acc, tid, SL);
    build_half<1>(ka, 1, 0, Wsm, acc);
    build_half<0>(kb, 1, 8, Wsm, acc);
    store_S(acc, tid, SR);
    __syncthreads();

    // ---- prefetch kk2-h0 behind mm1 (peak ~ acc1 32 + ka 16 + staging)
    load_half(KT2, tid, 0, ka);
    ull acc1[16];
    mmk(SL + w * SLOT, SR + w * SLOT, r, c, acc1);
    __syncthreads();   // mm1 reads done; SL/SR reusable

    // ---- phase 2 builds: S2T -> SL, S3T -> SR
    build_half<1>(ka, 2, 0, Wsm, acc);
    load_half(KT2, tid, 1, ka);
    build_half<0>(ka, 2, 8, Wsm, acc);
    store_S(acc, tid, SL);
    load_half(KT3, tid, 0, ka);
    load_half(KT3, tid, 1, kb);
    build_half<1>(ka, 3, 0, Wsm, acc);
    build_half<0>(kb, 3, 8, Wsm, acc);
    store_S(acc, tid, SR);
    __syncthreads();

    // ---- mm2: BT = S3T @ S2T = (S2 S3)^T ; out = sum A .* BT
    {
        ull acc2[16];
        mmk(SR + w * SLOT, SL + w * SLOT, r, c, acc2);
        ull t = 0ull;
        #pragma unroll
        for (int i = 0; i < 16; i++) t = fma2_(acc1[i], acc2[i], t);
        float tl, th; upk2(t, tl, th);
        float pacc = tl + th;
        #pragma unroll
        for (int o = 16; o; o >>= 1)
            pacc += __shfl_xor_sync(0xffffffffu, pacc, o);
        if (lane == 0) out[(b0 + w) * 64 + u] = pacc;
    }
}

extern "C" void kernel_launch(void* const* d_in, const int* in_sizes, int n_in,
                              void* d_out, int out_size) {
    const float* X = (const float*)d_in[0];
    const float* K = (const float*)d_in[1];
    if (in_sizes[0] != B_ * F_ * D_) {
        X = (const float*)d_in[1];
        K = (const float*)d_in[0];
    }
    const int pre_smem = PRE_FLOATS * 4;
    cudaFuncSetAttribute(kk_precompute, cudaFuncAttributeMaxDynamicSharedMemorySize,
                         pre_smem);
    cudaFuncSetAttribute(ring_main, cudaFuncAttributeMaxDynamicSharedMemorySize,
                         SMEM_FLOATS * 4);
    kk_precompute<<<128, 512, pre_smem>>>(K);
    ring_main<<<64 * 64, 256, SMEM_FLOATS * 4>>>(X, (float*)d_out);
}